// round 5
// baseline (speedup 1.0000x reference)
#include <cuda_runtime.h>
#include <cuda_bf16.h>
#include <math.h>

// Problem constants
#define BATCH   8192
#define FEAT    1024
#define DDIM    4096
#define NSCALE  5
#define NNODES  7
#define NLEAVES 8
#define HID     64
#define NH      448   // NNODES*HID
#define DH      256   // FEAT/4
#define MTOT    704   // NH + DH
#define LN_EPS  1e-5f

// Scratch: mid[b, m]  m<448 -> h (pre-LN, bias added); m>=448 -> d pre-gelu (bias added)
__device__ float g_mid[BATCH * MTOT];

__device__ __forceinline__ float gelu_exact(float x) {
    return 0.5f * x * (1.0f + erff(x * 0.70710678118654752440f));
}

// ---------------------------------------------------------------------------
// Kernel 1: fused SGEMM  C[b, m] = sum_f A[b,f] * W(m,f) + bias(m)
//   W(m,f) = tw1[m*1024+f]           (m < 448)
//          = dw1[(m-448)*1024+f]     (m >= 448)
// Tile: BM=128, BN=64, BK=16, 256 threads, 8x4 microtile.
// ---------------------------------------------------------------------------
#define BM 128
#define BN 64
#define BK 16

__global__ __launch_bounds__(256, 2)
void gemm_kernel(const float* __restrict__ A,
                 const float* __restrict__ tw1,
                 const float* __restrict__ dw1,
                 const float* __restrict__ tb1,
                 const float* __restrict__ db1)
{
    __shared__ float As[BK][BM];
    __shared__ float Bs[BK][BN];

    const int tid = threadIdx.x;
    const int bm = blockIdx.y * BM;
    const int bn = blockIdx.x * BN;

    const int tm = tid >> 4;        // 0..15 (m groups of 8)
    const int tn = tid & 15;        // 0..15 (n groups of 4)

    // Load assignments
    const int lr = tid >> 2;        // 0..63
    const int lk = (tid & 3) * 4;   // 0,4,8,12

    // A rows: bm+lr and bm+lr+64
    const float* Arow0 = A + (size_t)(bm + lr) * FEAT;
    const float* Arow1 = A + (size_t)(bm + lr + 64) * FEAT;
    // B (weight) row: n = bn + lr
    const int gn = bn + lr;
    const float* Brow = (gn < NH) ? (tw1 + (size_t)gn * FEAT)
                                  : (dw1 + (size_t)(gn - NH) * FEAT);

    float acc[8][4];
#pragma unroll
    for (int i = 0; i < 8; i++)
#pragma unroll
        for (int j = 0; j < 4; j++) acc[i][j] = 0.0f;

    for (int k0 = 0; k0 < FEAT; k0 += BK) {
        float4 a0 = *reinterpret_cast<const float4*>(Arow0 + k0 + lk);
        float4 a1 = *reinterpret_cast<const float4*>(Arow1 + k0 + lk);
        float4 b0 = *reinterpret_cast<const float4*>(Brow + k0 + lk);

        As[lk + 0][lr] = a0.x; As[lk + 1][lr] = a0.y;
        As[lk + 2][lr] = a0.z; As[lk + 3][lr] = a0.w;
        As[lk + 0][lr + 64] = a1.x; As[lk + 1][lr + 64] = a1.y;
        As[lk + 2][lr + 64] = a1.z; As[lk + 3][lr + 64] = a1.w;
        Bs[lk + 0][lr] = b0.x; Bs[lk + 1][lr] = b0.y;
        Bs[lk + 2][lr] = b0.z; Bs[lk + 3][lr] = b0.w;
        __syncthreads();

#pragma unroll
        for (int k = 0; k < BK; k++) {
            float4 av0 = *reinterpret_cast<const float4*>(&As[k][tm * 8]);
            float4 av1 = *reinterpret_cast<const float4*>(&As[k][tm * 8 + 4]);
            float4 bv  = *reinterpret_cast<const float4*>(&Bs[k][tn * 4]);
            float am[8] = {av0.x, av0.y, av0.z, av0.w, av1.x, av1.y, av1.z, av1.w};
            float bm_[4] = {bv.x, bv.y, bv.z, bv.w};
#pragma unroll
            for (int i = 0; i < 8; i++)
#pragma unroll
                for (int j = 0; j < 4; j++)
                    acc[i][j] = fmaf(am[i], bm_[j], acc[i][j]);
        }
        __syncthreads();
    }

    // Epilogue: add bias, write to scratch
    const int n0 = bn + tn * 4;
#pragma unroll
    for (int j = 0; j < 4; j++) {
        int c = n0 + j;
        float bias = (c < NH) ? tb1[c] : db1[c - NH];
#pragma unroll
        for (int i = 0; i < 8; i++) {
            int m = bm + tm * 8 + i;
            g_mid[(size_t)m * MTOT + c] = acc[i][j] + bias;
        }
    }
}

// ---------------------------------------------------------------------------
// Kernel 2: per-row gating. One warp per batch row.
// ---------------------------------------------------------------------------
__global__ __launch_bounds__(256)
void gating_kernel(const float* __restrict__ tg,
                   const float* __restrict__ tbn,
                   const float* __restrict__ tw2,
                   const float* __restrict__ tb2,
                   const float* __restrict__ lw1,
                   const float* __restrict__ lb1,
                   const float* __restrict__ lw2,
                   const float* __restrict__ lb2,
                   const float* __restrict__ dw2,
                   const float* __restrict__ db2,
                   const float* __restrict__ cw,
                   float* __restrict__ gates_out)  // [BATCH,5]
{
    const int warp = (blockIdx.x * blockDim.x + threadIdx.x) >> 5;
    const int lane = threadIdx.x & 31;
    if (warp >= BATCH) return;

    const float* row = g_mid + (size_t)warp * MTOT;

    // ----- tree nodes: LN + gelu + node logits + softmax(T=0.5) -----
    float pright[NNODES];
#pragma unroll
    for (int n = 0; n < NNODES; n++) {
        float v0 = row[n * 64 + lane];
        float v1 = row[n * 64 + lane + 32];
        float s = v0 + v1;
        float q = v0 * v0 + v1 * v1;
#pragma unroll
        for (int o = 16; o > 0; o >>= 1) {
            s += __shfl_xor_sync(0xffffffffu, s, o);
            q += __shfl_xor_sync(0xffffffffu, q, o);
        }
        float mean = s * (1.0f / 64.0f);
        float var  = q * (1.0f / 64.0f) - mean * mean;
        float rstd = rsqrtf(var + LN_EPS);
        float g0 = gelu_exact((v0 - mean) * rstd * tg[n * 64 + lane] + tbn[n * 64 + lane]);
        float g1 = gelu_exact((v1 - mean) * rstd * tg[n * 64 + lane + 32] + tbn[n * 64 + lane + 32]);
        float z0 = g0 * tw2[n * 128 + lane]      + g1 * tw2[n * 128 + lane + 32];
        float z1 = g0 * tw2[n * 128 + 64 + lane] + g1 * tw2[n * 128 + 64 + lane + 32];
#pragma unroll
        for (int o = 16; o > 0; o >>= 1) {
            z0 += __shfl_xor_sync(0xffffffffu, z0, o);
            z1 += __shfl_xor_sync(0xffffffffu, z1, o);
        }
        z0 += tb2[n * 2 + 0];
        z1 += tb2[n * 2 + 1];
        // softmax([z0,z1]/0.5)[1] = sigmoid(2*(z1-z0))
        pright[n] = 1.0f / (1.0f + expf(-2.0f * (z1 - z0)));
    }

    // ----- leaf probabilities (replicated per-lane; tiny) -----
    float leaf[NLEAVES];
#pragma unroll
    for (int l = 0; l < NLEAVES; l++) {
        int b2 = (l >> 2) & 1, b1 = (l >> 1) & 1, b0 = l & 1;
        float p2 = b2 ? pright[0] : (1.0f - pright[0]);
        int n1 = 1 + b2;
        float p1 = b1 ? pright[n1] : (1.0f - pright[n1]);
        int n2 = 3 + b2 * 2 + b1;
        float p0 = b0 ? pright[n2] : (1.0f - pright[n2]);
        leaf[l] = p2 * p1 * p0;
    }

    // ----- tree gate head -----
    float t[2 * NSCALE];
#pragma unroll
    for (int j = 0; j < 2 * NSCALE; j++) {
        float a = lb1[j];
#pragma unroll
        for (int l = 0; l < NLEAVES; l++) a += leaf[l] * lw1[j * NLEAVES + l];
        t[j] = gelu_exact(a);
    }
    float tz[NSCALE];
    float tmax = -1e30f;
#pragma unroll
    for (int sIdx = 0; sIdx < NSCALE; sIdx++) {
        float a = lb2[sIdx];
#pragma unroll
        for (int j = 0; j < 2 * NSCALE; j++) a += t[j] * lw2[sIdx * 2 * NSCALE + j];
        tz[sIdx] = a;
        tmax = fmaxf(tmax, a);
    }
    float tsum = 0.0f;
#pragma unroll
    for (int sIdx = 0; sIdx < NSCALE; sIdx++) { tz[sIdx] = expf(tz[sIdx] - tmax); tsum += tz[sIdx]; }
    float tinv = 1.0f / tsum;
#pragma unroll
    for (int sIdx = 0; sIdx < NSCALE; sIdx++) tz[sIdx] *= tinv;

    // ----- direct gate head -----
    float acc5[NSCALE];
#pragma unroll
    for (int sIdx = 0; sIdx < NSCALE; sIdx++) acc5[sIdx] = 0.0f;
#pragma unroll
    for (int r = 0; r < DH / 32; r++) {
        int idx = r * 32 + lane;
        float dg = gelu_exact(row[NH + idx]);
#pragma unroll
        for (int sIdx = 0; sIdx < NSCALE; sIdx++)
            acc5[sIdx] += dg * dw2[sIdx * DH + idx];
    }
#pragma unroll
    for (int sIdx = 0; sIdx < NSCALE; sIdx++) {
        float a = acc5[sIdx];
#pragma unroll
        for (int o = 16; o > 0; o >>= 1) a += __shfl_xor_sync(0xffffffffu, a, o);
        acc5[sIdx] = a + db2[sIdx];
    }
    float dmax = -1e30f;
#pragma unroll
    for (int sIdx = 0; sIdx < NSCALE; sIdx++) dmax = fmaxf(dmax, acc5[sIdx]);
    float dsum = 0.0f;
#pragma unroll
    for (int sIdx = 0; sIdx < NSCALE; sIdx++) { acc5[sIdx] = expf(acc5[sIdx] - dmax); dsum += acc5[sIdx]; }
    float dinv = 1.0f / dsum;
#pragma unroll
    for (int sIdx = 0; sIdx < NSCALE; sIdx++) acc5[sIdx] *= dinv;

    // ----- combine + renormalize -----
    float w = 1.0f / (1.0f + expf(-cw[0]));
    float g[NSCALE];
    float gs = 0.0f;
#pragma unroll
    for (int sIdx = 0; sIdx < NSCALE; sIdx++) {
        g[sIdx] = w * tz[sIdx] + (1.0f - w) * acc5[sIdx];
        gs += g[sIdx];
    }
    float ginv = 1.0f / gs;
    if (lane < NSCALE)
        gates_out[(size_t)warp * NSCALE + lane] = g[lane] * ginv;
}

// ---------------------------------------------------------------------------
// Kernel 3: combined[b,d] = sum_s gates[b,s] * logits[s,b,d]
// One block per row, float4 vectorized. Memory-bound.
// ---------------------------------------------------------------------------
__global__ __launch_bounds__(256)
void combine_kernel(const float* __restrict__ logits,
                    const float* __restrict__ gates,
                    float* __restrict__ out)
{
    const int b = blockIdx.x;
    const float* gp = gates + (size_t)b * NSCALE;
    float g0 = __ldg(gp + 0), g1 = __ldg(gp + 1), g2 = __ldg(gp + 2),
          g3 = __ldg(gp + 3), g4 = __ldg(gp + 4);

    const size_t rowoff = (size_t)b * DDIM;
    const size_t plane  = (size_t)BATCH * DDIM;

#pragma unroll
    for (int it = 0; it < DDIM / (256 * 4); it++) {
        int col = it * 1024 + threadIdx.x * 4;
        float4 v0 = *reinterpret_cast<const float4*>(logits + 0 * plane + rowoff + col);
        float4 v1 = *reinterpret_cast<const float4*>(logits + 1 * plane + rowoff + col);
        float4 v2 = *reinterpret_cast<const float4*>(logits + 2 * plane + rowoff + col);
        float4 v3 = *reinterpret_cast<const float4*>(logits + 3 * plane + rowoff + col);
        float4 v4 = *reinterpret_cast<const float4*>(logits + 4 * plane + rowoff + col);
        float4 r;
        r.x = g0 * v0.x + g1 * v1.x + g2 * v2.x + g3 * v3.x + g4 * v4.x;
        r.y = g0 * v0.y + g1 * v1.y + g2 * v2.y + g3 * v3.y + g4 * v4.y;
        r.z = g0 * v0.z + g1 * v1.z + g2 * v2.z + g3 * v3.z + g4 * v4.z;
        r.w = g0 * v0.w + g1 * v1.w + g2 * v2.w + g3 * v3.w + g4 * v4.w;
        *reinterpret_cast<float4*>(out + rowoff + col) = r;
    }
}

// ---------------------------------------------------------------------------
// Launcher. d_out layout: [combined (8192*4096 f32)] [gates (8192*5 f32)]
// Inputs (metadata order):
// 0 features 1 logits 2 tw1 3 tb1 4 tg 5 tbn 6 tw2 7 tb2 8 lw1 9 lb1
// 10 lw2 11 lb2 12 dw1 13 db1 14 dw2 15 db2 16 combine_weight
// ---------------------------------------------------------------------------
extern "C" void kernel_launch(void* const* d_in, const int* in_sizes, int n_in,
                              void* d_out, int out_size)
{
    const float* features = (const float*)d_in[0];
    const float* logits   = (const float*)d_in[1];
    const float* tw1      = (const float*)d_in[2];
    const float* tb1      = (const float*)d_in[3];
    const float* tg       = (const float*)d_in[4];
    const float* tbn      = (const float*)d_in[5];
    const float* tw2      = (const float*)d_in[6];
    const float* tb2      = (const float*)d_in[7];
    const float* lw1      = (const float*)d_in[8];
    const float* lb1      = (const float*)d_in[9];
    const float* lw2      = (const float*)d_in[10];
    const float* lb2      = (const float*)d_in[11];
    const float* dw1      = (const float*)d_in[12];
    const float* db1      = (const float*)d_in[13];
    const float* dw2      = (const float*)d_in[14];
    const float* db2      = (const float*)d_in[15];
    const float* cw       = (const float*)d_in[16];

    float* out = (float*)d_out;
    float* gates_out = out + (size_t)BATCH * DDIM;

    dim3 gemm_grid(MTOT / BN, BATCH / BM);  // (11, 64)
    gemm_kernel<<<gemm_grid, 256>>>(features, tw1, dw1, tb1, db1);

    // 8192 warps -> 1024 blocks of 256 threads (8 warps each)
    gating_kernel<<<BATCH / 8, 256>>>(tg, tbn, tw2, tb2, lw1, lb1, lw2, lb2,
                                      dw2, db2, cw, gates_out);

    combine_kernel<<<BATCH, 256>>>(logits, gates_out, out);
}

// round 6
// speedup vs baseline: 1.8074x; 1.8074x over previous
#include <cuda_runtime.h>
#include <cuda_bf16.h>
#include <math.h>
#include <stdint.h>

// Problem constants
#define BATCH   8192
#define FEAT    1024
#define DDIM    4096
#define NSCALE  5
#define NNODES  7
#define NLEAVES 8
#define HID     64
#define NH      448   // NNODES*HID
#define DH      256   // FEAT/4
#define MTOT    704   // NH + DH
#define LN_EPS  1e-5f

// Scratch: mid[b, m]  m<448 -> h (pre-LN, bias added); m>=448 -> d pre-gelu (bias added)
__device__ float g_mid[BATCH * MTOT];

__device__ __forceinline__ float gelu_exact(float x) {
    return 0.5f * x * (1.0f + erff(x * 0.70710678118654752440f));
}

__device__ __forceinline__ uint32_t f2tf32(float x) {
    uint32_t y;
    asm("cvt.rna.tf32.f32 %0, %1;" : "=r"(y) : "f"(x));
    return y;
}

__device__ __forceinline__ void mma_tf32(float c[4],
                                         uint32_t a0, uint32_t a1, uint32_t a2, uint32_t a3,
                                         uint32_t b0, uint32_t b1) {
    asm volatile(
        "mma.sync.aligned.m16n8k8.row.col.f32.tf32.tf32.f32 "
        "{%0,%1,%2,%3}, {%4,%5,%6,%7}, {%8,%9}, {%0,%1,%2,%3};\n"
        : "+f"(c[0]), "+f"(c[1]), "+f"(c[2]), "+f"(c[3])
        : "r"(a0), "r"(a1), "r"(a2), "r"(a3), "r"(b0), "r"(b1));
}

// ---------------------------------------------------------------------------
// Kernel 1: tensor-core tf32 SGEMM  C[b, m] = sum_f A[b,f] * W(m,f) + bias(m)
//   W(m,f) = tw1[m*1024+f] (m<448) | dw1[(m-448)*1024+f] (m>=448)
// BM=128, BN=64, BK=32, 256 thr, warp grid 4(M)x2(N), warp tile 32x32.
// Smem row stride 36 words: conflict-free scalar LDS fragment loads and
// conflict-free uint4 stores.
// ---------------------------------------------------------------------------
#define BM 128
#define BN 64
#define BK 32
#define SSTRIDE 36

__global__ __launch_bounds__(256, 2)
void gemm_tc_kernel(const float* __restrict__ A,
                    const float* __restrict__ tw1,
                    const float* __restrict__ dw1,
                    const float* __restrict__ tb1,
                    const float* __restrict__ db1)
{
    __shared__ uint32_t As[BM * SSTRIDE];   // 18432 B
    __shared__ uint32_t Bs[BN * SSTRIDE];   //  9216 B

    const int tid  = threadIdx.x;
    const int lane = tid & 31;
    const int warp = tid >> 5;
    const int g    = lane >> 2;   // group 0..7
    const int t    = lane & 3;    // thread-in-group 0..3
    const int warpM = warp >> 1;  // 0..3
    const int warpN = warp & 1;   // 0..1

    const int bm = blockIdx.y * BM;
    const int bn = blockIdx.x * BN;

    // ---- global load assignments ----
    // A: 128 rows x 8 float4 (32 cols) = 1024 f4 -> 4 per thread
    const int lrow = tid >> 3;          // 0..31 (rows lrow + i*32)
    const int lc4  = (tid & 7) * 4;     // col offset 0..28
    const float* ap = A + (size_t)(bm + lrow) * FEAT + lc4;
    // B: 64 rows x 8 f4 = 512 f4 -> 2 per thread (rows lrow, lrow+32)
    const int gn0 = bn + lrow;
    const int gn1 = bn + lrow + 32;
    const float* bp0 = (gn0 < NH) ? (tw1 + (size_t)gn0 * FEAT + lc4)
                                  : (dw1 + (size_t)(gn0 - NH) * FEAT + lc4);
    const float* bp1 = (gn1 < NH) ? (tw1 + (size_t)gn1 * FEAT + lc4)
                                  : (dw1 + (size_t)(gn1 - NH) * FEAT + lc4);

    float4 ra[4], rb[2];
#pragma unroll
    for (int i = 0; i < 4; i++)
        ra[i] = *reinterpret_cast<const float4*>(ap + (size_t)i * 32 * FEAT);
    rb[0] = *reinterpret_cast<const float4*>(bp0);
    rb[1] = *reinterpret_cast<const float4*>(bp1);

    float acc[2][4][4];
#pragma unroll
    for (int mt = 0; mt < 2; mt++)
#pragma unroll
        for (int nt = 0; nt < 4; nt++)
#pragma unroll
            for (int i = 0; i < 4; i++) acc[mt][nt][i] = 0.0f;

    const int NITER = FEAT / BK;  // 32
    for (int k0 = 0; k0 < NITER; k0++) {
        // store prefetched regs -> smem (tf32 converted, uint4)
#pragma unroll
        for (int i = 0; i < 4; i++) {
            uint4 v = make_uint4(f2tf32(ra[i].x), f2tf32(ra[i].y),
                                 f2tf32(ra[i].z), f2tf32(ra[i].w));
            *reinterpret_cast<uint4*>(&As[(lrow + i * 32) * SSTRIDE + lc4]) = v;
        }
        {
            uint4 v0 = make_uint4(f2tf32(rb[0].x), f2tf32(rb[0].y),
                                  f2tf32(rb[0].z), f2tf32(rb[0].w));
            uint4 v1 = make_uint4(f2tf32(rb[1].x), f2tf32(rb[1].y),
                                  f2tf32(rb[1].z), f2tf32(rb[1].w));
            *reinterpret_cast<uint4*>(&Bs[lrow * SSTRIDE + lc4]) = v0;
            *reinterpret_cast<uint4*>(&Bs[(lrow + 32) * SSTRIDE + lc4]) = v1;
        }
        __syncthreads();

        // prefetch next K-slab
        if (k0 + 1 < NITER) {
            const int ko = (k0 + 1) * BK;
#pragma unroll
            for (int i = 0; i < 4; i++)
                ra[i] = *reinterpret_cast<const float4*>(ap + (size_t)i * 32 * FEAT + ko);
            rb[0] = *reinterpret_cast<const float4*>(bp0 + ko);
            rb[1] = *reinterpret_cast<const float4*>(bp1 + ko);
        }

        // compute: 4 k-steps of 8
#pragma unroll
        for (int ks = 0; ks < 4; ks++) {
            const int ko = ks * 8;
            uint32_t af[2][4], bf[4][2];
#pragma unroll
            for (int mt = 0; mt < 2; mt++) {
                const int r0 = (warpM * 32 + mt * 16 + g) * SSTRIDE + ko + t;
                af[mt][0] = As[r0];
                af[mt][2] = As[r0 + 4];
                af[mt][1] = As[r0 + 8 * SSTRIDE];
                af[mt][3] = As[r0 + 8 * SSTRIDE + 4];
            }
#pragma unroll
            for (int nt = 0; nt < 4; nt++) {
                const int r0 = (warpN * 32 + nt * 8 + g) * SSTRIDE + ko + t;
                bf[nt][0] = Bs[r0];
                bf[nt][1] = Bs[r0 + 4];
            }
#pragma unroll
            for (int mt = 0; mt < 2; mt++)
#pragma unroll
                for (int nt = 0; nt < 4; nt++)
                    mma_tf32(acc[mt][nt], af[mt][0], af[mt][1], af[mt][2], af[mt][3],
                             bf[nt][0], bf[nt][1]);
        }
        __syncthreads();
    }

    // ---- epilogue: add bias, write to scratch ----
#pragma unroll
    for (int nt = 0; nt < 4; nt++) {
        const int col = bn + warpN * 32 + nt * 8 + 2 * t;
        const float bias0 = (col < NH) ? tb1[col] : db1[col - NH];
        const float bias1 = (col + 1 < NH) ? tb1[col + 1] : db1[col + 1 - NH];
#pragma unroll
        for (int mt = 0; mt < 2; mt++) {
            const int row = bm + warpM * 32 + mt * 16 + g;
            float2 lo = make_float2(acc[mt][nt][0] + bias0, acc[mt][nt][1] + bias1);
            float2 hi = make_float2(acc[mt][nt][2] + bias0, acc[mt][nt][3] + bias1);
            *reinterpret_cast<float2*>(&g_mid[(size_t)row * MTOT + col]) = lo;
            *reinterpret_cast<float2*>(&g_mid[(size_t)(row + 8) * MTOT + col]) = hi;
        }
    }
}

// ---------------------------------------------------------------------------
// Kernel 2: per-row gating. One warp per batch row.
// ---------------------------------------------------------------------------
__global__ __launch_bounds__(256)
void gating_kernel(const float* __restrict__ tg,
                   const float* __restrict__ tbn,
                   const float* __restrict__ tw2,
                   const float* __restrict__ tb2,
                   const float* __restrict__ lw1,
                   const float* __restrict__ lb1,
                   const float* __restrict__ lw2,
                   const float* __restrict__ lb2,
                   const float* __restrict__ dw2,
                   const float* __restrict__ db2,
                   const float* __restrict__ cw,
                   float* __restrict__ gates_out)  // [BATCH,5]
{
    const int warp = (blockIdx.x * blockDim.x + threadIdx.x) >> 5;
    const int lane = threadIdx.x & 31;
    if (warp >= BATCH) return;

    const float* row = g_mid + (size_t)warp * MTOT;

    // ----- tree nodes: LN + gelu + node logits + softmax(T=0.5) -----
    float pright[NNODES];
#pragma unroll
    for (int n = 0; n < NNODES; n++) {
        float v0 = row[n * 64 + lane];
        float v1 = row[n * 64 + lane + 32];
        float s = v0 + v1;
        float q = v0 * v0 + v1 * v1;
#pragma unroll
        for (int o = 16; o > 0; o >>= 1) {
            s += __shfl_xor_sync(0xffffffffu, s, o);
            q += __shfl_xor_sync(0xffffffffu, q, o);
        }
        float mean = s * (1.0f / 64.0f);
        float var  = q * (1.0f / 64.0f) - mean * mean;
        float rstd = rsqrtf(var + LN_EPS);
        float g0 = gelu_exact((v0 - mean) * rstd * tg[n * 64 + lane] + tbn[n * 64 + lane]);
        float g1 = gelu_exact((v1 - mean) * rstd * tg[n * 64 + lane + 32] + tbn[n * 64 + lane + 32]);
        float z0 = g0 * tw2[n * 128 + lane]      + g1 * tw2[n * 128 + lane + 32];
        float z1 = g0 * tw2[n * 128 + 64 + lane] + g1 * tw2[n * 128 + 64 + lane + 32];
#pragma unroll
        for (int o = 16; o > 0; o >>= 1) {
            z0 += __shfl_xor_sync(0xffffffffu, z0, o);
            z1 += __shfl_xor_sync(0xffffffffu, z1, o);
        }
        z0 += tb2[n * 2 + 0];
        z1 += tb2[n * 2 + 1];
        // softmax([z0,z1]/0.5)[1] = sigmoid(2*(z1-z0))
        pright[n] = 1.0f / (1.0f + expf(-2.0f * (z1 - z0)));
    }

    // ----- leaf probabilities -----
    float leaf[NLEAVES];
#pragma unroll
    for (int l = 0; l < NLEAVES; l++) {
        int b2 = (l >> 2) & 1, b1 = (l >> 1) & 1, b0 = l & 1;
        float p2 = b2 ? pright[0] : (1.0f - pright[0]);
        int n1 = 1 + b2;
        float p1 = b1 ? pright[n1] : (1.0f - pright[n1]);
        int n2 = 3 + b2 * 2 + b1;
        float p0 = b0 ? pright[n2] : (1.0f - pright[n2]);
        leaf[l] = p2 * p1 * p0;
    }

    // ----- tree gate head -----
    float t[2 * NSCALE];
#pragma unroll
    for (int j = 0; j < 2 * NSCALE; j++) {
        float a = lb1[j];
#pragma unroll
        for (int l = 0; l < NLEAVES; l++) a += leaf[l] * lw1[j * NLEAVES + l];
        t[j] = gelu_exact(a);
    }
    float tz[NSCALE];
    float tmax = -1e30f;
#pragma unroll
    for (int sIdx = 0; sIdx < NSCALE; sIdx++) {
        float a = lb2[sIdx];
#pragma unroll
        for (int j = 0; j < 2 * NSCALE; j++) a += t[j] * lw2[sIdx * 2 * NSCALE + j];
        tz[sIdx] = a;
        tmax = fmaxf(tmax, a);
    }
    float tsum = 0.0f;
#pragma unroll
    for (int sIdx = 0; sIdx < NSCALE; sIdx++) { tz[sIdx] = expf(tz[sIdx] - tmax); tsum += tz[sIdx]; }
    float tinv = 1.0f / tsum;
#pragma unroll
    for (int sIdx = 0; sIdx < NSCALE; sIdx++) tz[sIdx] *= tinv;

    // ----- direct gate head -----
    float acc5[NSCALE];
#pragma unroll
    for (int sIdx = 0; sIdx < NSCALE; sIdx++) acc5[sIdx] = 0.0f;
#pragma unroll
    for (int r = 0; r < DH / 32; r++) {
        int idx = r * 32 + lane;
        float dg = gelu_exact(row[NH + idx]);
#pragma unroll
        for (int sIdx = 0; sIdx < NSCALE; sIdx++)
            acc5[sIdx] += dg * dw2[sIdx * DH + idx];
    }
#pragma unroll
    for (int sIdx = 0; sIdx < NSCALE; sIdx++) {
        float a = acc5[sIdx];
#pragma unroll
        for (int o = 16; o > 0; o >>= 1) a += __shfl_xor_sync(0xffffffffu, a, o);
        acc5[sIdx] = a + db2[sIdx];
    }
    float dmax = -1e30f;
#pragma unroll
    for (int sIdx = 0; sIdx < NSCALE; sIdx++) dmax = fmaxf(dmax, acc5[sIdx]);
    float dsum = 0.0f;
#pragma unroll
    for (int sIdx = 0; sIdx < NSCALE; sIdx++) { acc5[sIdx] = expf(acc5[sIdx] - dmax); dsum += acc5[sIdx]; }
    float dinv = 1.0f / dsum;
#pragma unroll
    for (int sIdx = 0; sIdx < NSCALE; sIdx++) acc5[sIdx] *= dinv;

    // ----- combine + renormalize -----
    float w = 1.0f / (1.0f + expf(-cw[0]));
    float gg[NSCALE];
    float gs = 0.0f;
#pragma unroll
    for (int sIdx = 0; sIdx < NSCALE; sIdx++) {
        gg[sIdx] = w * tz[sIdx] + (1.0f - w) * acc5[sIdx];
        gs += gg[sIdx];
    }
    float ginv = 1.0f / gs;
    if (lane < NSCALE)
        gates_out[(size_t)warp * NSCALE + lane] = gg[lane] * ginv;
}

// ---------------------------------------------------------------------------
// Kernel 3: combined[b,d] = sum_s gates[b,s] * logits[s,b,d]
// ---------------------------------------------------------------------------
__global__ __launch_bounds__(256)
void combine_kernel(const float* __restrict__ logits,
                    const float* __restrict__ gates,
                    float* __restrict__ out)
{
    const int b = blockIdx.x;
    const float* gp = gates + (size_t)b * NSCALE;
    float g0 = __ldg(gp + 0), g1 = __ldg(gp + 1), g2 = __ldg(gp + 2),
          g3 = __ldg(gp + 3), g4 = __ldg(gp + 4);

    const size_t rowoff = (size_t)b * DDIM;
    const size_t plane  = (size_t)BATCH * DDIM;

#pragma unroll
    for (int it = 0; it < DDIM / (256 * 4); it++) {
        int col = it * 1024 + threadIdx.x * 4;
        float4 v0 = *reinterpret_cast<const float4*>(logits + 0 * plane + rowoff + col);
        float4 v1 = *reinterpret_cast<const float4*>(logits + 1 * plane + rowoff + col);
        float4 v2 = *reinterpret_cast<const float4*>(logits + 2 * plane + rowoff + col);
        float4 v3 = *reinterpret_cast<const float4*>(logits + 3 * plane + rowoff + col);
        float4 v4 = *reinterpret_cast<const float4*>(logits + 4 * plane + rowoff + col);
        float4 r;
        r.x = g0 * v0.x + g1 * v1.x + g2 * v2.x + g3 * v3.x + g4 * v4.x;
        r.y = g0 * v0.y + g1 * v1.y + g2 * v2.y + g3 * v3.y + g4 * v4.y;
        r.z = g0 * v0.z + g1 * v1.z + g2 * v2.z + g3 * v3.z + g4 * v4.z;
        r.w = g0 * v0.w + g1 * v1.w + g2 * v2.w + g3 * v3.w + g4 * v4.w;
        *reinterpret_cast<float4*>(out + rowoff + col) = r;
    }
}

// ---------------------------------------------------------------------------
// Launcher. d_out layout: [combined (8192*4096 f32)] [gates (8192*5 f32)]
// ---------------------------------------------------------------------------
extern "C" void kernel_launch(void* const* d_in, const int* in_sizes, int n_in,
                              void* d_out, int out_size)
{
    const float* features = (const float*)d_in[0];
    const float* logits   = (const float*)d_in[1];
    const float* tw1      = (const float*)d_in[2];
    const float* tb1      = (const float*)d_in[3];
    const float* tg       = (const float*)d_in[4];
    const float* tbn      = (const float*)d_in[5];
    const float* tw2      = (const float*)d_in[6];
    const float* tb2      = (const float*)d_in[7];
    const float* lw1      = (const float*)d_in[8];
    const float* lb1      = (const float*)d_in[9];
    const float* lw2      = (const float*)d_in[10];
    const float* lb2      = (const float*)d_in[11];
    const float* dw1      = (const float*)d_in[12];
    const float* db1      = (const float*)d_in[13];
    const float* dw2      = (const float*)d_in[14];
    const float* db2      = (const float*)d_in[15];
    const float* cw       = (const float*)d_in[16];

    float* out = (float*)d_out;
    float* gates_out = out + (size_t)BATCH * DDIM;

    dim3 gemm_grid(MTOT / BN, BATCH / BM);  // (11, 64)
    gemm_tc_kernel<<<gemm_grid, 256>>>(features, tw1, dw1, tb1, db1);

    gating_kernel<<<BATCH / 8, 256>>>(tg, tbn, tw2, tb2, lw1, lb1, lw2, lb2,
                                      dw2, db2, cw, gates_out);

    combine_kernel<<<BATCH, 256>>>(logits, gates_out, out);
}

// round 7
// speedup vs baseline: 1.9125x; 1.0581x over previous
#include <cuda_runtime.h>
#include <cuda_bf16.h>
#include <math.h>
#include <stdint.h>

// Problem constants
#define BATCH   8192
#define FEAT    1024
#define DDIM    4096
#define NSCALE  5
#define NNODES  7
#define NLEAVES 8
#define HID     64
#define NH      448   // NNODES*HID
#define DH      256   // FEAT/4
#define MTOT    704   // NH + DH
#define LN_EPS  1e-5f

// Scratch: mid[b, m]  m<448 -> h (pre-LN, bias added); m>=448 -> d pre-gelu (bias added)
__device__ float g_mid[BATCH * MTOT];

__device__ __forceinline__ float gelu_exact(float x) {
    return 0.5f * x * (1.0f + erff(x * 0.70710678118654752440f));
}

__device__ __forceinline__ uint2 f4_to_bf16x4(float4 v) {
    __nv_bfloat162 lo = __floats2bfloat162_rn(v.x, v.y);
    __nv_bfloat162 hi = __floats2bfloat162_rn(v.z, v.w);
    uint2 r;
    r.x = *reinterpret_cast<uint32_t*>(&lo);
    r.y = *reinterpret_cast<uint32_t*>(&hi);
    return r;
}

__device__ __forceinline__ void mma_bf16(float c[4],
                                         uint32_t a0, uint32_t a1, uint32_t a2, uint32_t a3,
                                         uint32_t b0, uint32_t b1) {
    asm volatile(
        "mma.sync.aligned.m16n8k16.row.col.f32.bf16.bf16.f32 "
        "{%0,%1,%2,%3}, {%4,%5,%6,%7}, {%8,%9}, {%0,%1,%2,%3};\n"
        : "+f"(c[0]), "+f"(c[1]), "+f"(c[2]), "+f"(c[3])
        : "r"(a0), "r"(a1), "r"(a2), "r"(a3), "r"(b0), "r"(b1));
}

// ---------------------------------------------------------------------------
// Kernel 1: tensor-core bf16 GEMM  C[b, m] = sum_f A[b,f] * W(m,f) + bias(m)
//   W(m,f) = tw1[m*1024+f] (m<448) | dw1[(m-448)*1024+f] (m>=448)
// BM=256, BN=64, BK=32 (elements), 256 thr, warp grid 4(M)x2(N),
// warp tile 64x32 -> 16 MMAs per k16 step, 24 LDS phases per 16 MMAs.
// Smem as uint32 (bf16x2 pairs), row stride 20 words: conflict-free scalar
// LDS fragment loads (banks 20g+t mod 32 all distinct for g<8,t<4).
// ---------------------------------------------------------------------------
#define BM 256
#define BN 64
#define BK 32
#define S32 20   // uint32 stride per row (16 data words + 4 pad)

__global__ __launch_bounds__(256, 2)
void gemm_tc_kernel(const float* __restrict__ A,
                    const float* __restrict__ tw1,
                    const float* __restrict__ dw1,
                    const float* __restrict__ tb1,
                    const float* __restrict__ db1)
{
    __shared__ uint32_t As[BM * S32];   // 20480 B
    __shared__ uint32_t Bs[BN * S32];   //  5120 B

    const int tid  = threadIdx.x;
    const int lane = tid & 31;
    const int warp = tid >> 5;
    const int g    = lane >> 2;   // 0..7
    const int t    = lane & 3;    // 0..3
    const int warpM = warp >> 1;  // 0..3  (64-row slab)
    const int warpN = warp & 1;   // 0..1  (32-col slab)

    const int bm = blockIdx.y * BM;
    const int bn = blockIdx.x * BN;

    // ---- global load assignments ----
    const int lrow = tid >> 3;          // 0..31
    const int lc4  = (tid & 7) * 4;     // float col offset
    const int lc2  = (tid & 7) * 2;     // uint32 col offset in smem

    const float* ap = A + (size_t)(bm + lrow) * FEAT + lc4;
    const int gn0 = bn + lrow;
    const int gn1 = bn + lrow + 32;
    const float* bp0 = (gn0 < NH) ? (tw1 + (size_t)gn0 * FEAT + lc4)
                                  : (dw1 + (size_t)(gn0 - NH) * FEAT + lc4);
    const float* bp1 = (gn1 < NH) ? (tw1 + (size_t)gn1 * FEAT + lc4)
                                  : (dw1 + (size_t)(gn1 - NH) * FEAT + lc4);

    // prefetch slab 0 (converted to bf16 pairs immediately -> low reg count)
    uint2 pa[8], pb0, pb1;
#pragma unroll
    for (int i = 0; i < 8; i++)
        pa[i] = f4_to_bf16x4(*reinterpret_cast<const float4*>(ap + (size_t)i * 32 * FEAT));
    pb0 = f4_to_bf16x4(*reinterpret_cast<const float4*>(bp0));
    pb1 = f4_to_bf16x4(*reinterpret_cast<const float4*>(bp1));

    float acc[4][4][4];
#pragma unroll
    for (int mt = 0; mt < 4; mt++)
#pragma unroll
        for (int nt = 0; nt < 4; nt++)
#pragma unroll
            for (int i = 0; i < 4; i++) acc[mt][nt][i] = 0.0f;

    const int NITER = FEAT / BK;  // 32
    for (int k0 = 0; k0 < NITER; k0++) {
        // store prefetched slab
#pragma unroll
        for (int i = 0; i < 8; i++)
            *reinterpret_cast<uint2*>(&As[(lrow + i * 32) * S32 + lc2]) = pa[i];
        *reinterpret_cast<uint2*>(&Bs[lrow * S32 + lc2]) = pb0;
        *reinterpret_cast<uint2*>(&Bs[(lrow + 32) * S32 + lc2]) = pb1;
        __syncthreads();

        // prefetch next slab
        if (k0 + 1 < NITER) {
            const int ko = (k0 + 1) * BK;
#pragma unroll
            for (int i = 0; i < 8; i++)
                pa[i] = f4_to_bf16x4(*reinterpret_cast<const float4*>(ap + (size_t)i * 32 * FEAT + ko));
            pb0 = f4_to_bf16x4(*reinterpret_cast<const float4*>(bp0 + ko));
            pb1 = f4_to_bf16x4(*reinterpret_cast<const float4*>(bp1 + ko));
        }

        // compute: 2 k16 steps
#pragma unroll
        for (int ks = 0; ks < 2; ks++) {
            const int ko = ks * 8;
            uint32_t bf[4][2];
#pragma unroll
            for (int nt = 0; nt < 4; nt++) {
                const int r0 = (warpN * 32 + nt * 8 + g) * S32 + ko + t;
                bf[nt][0] = Bs[r0];
                bf[nt][1] = Bs[r0 + 4];
            }
#pragma unroll
            for (int mt = 0; mt < 4; mt++) {
                const int r0 = (warpM * 64 + mt * 16 + g) * S32 + ko + t;
                uint32_t a0 = As[r0];
                uint32_t a1 = As[r0 + 8 * S32];
                uint32_t a2 = As[r0 + 4];
                uint32_t a3 = As[r0 + 8 * S32 + 4];
#pragma unroll
                for (int nt = 0; nt < 4; nt++)
                    mma_bf16(acc[mt][nt], a0, a1, a2, a3, bf[nt][0], bf[nt][1]);
            }
        }
        __syncthreads();
    }

    // ---- epilogue: add bias, write to scratch ----
#pragma unroll
    for (int nt = 0; nt < 4; nt++) {
        const int col = bn + warpN * 32 + nt * 8 + 2 * t;
        const float bias0 = (col < NH) ? tb1[col] : db1[col - NH];
        const float bias1 = (col + 1 < NH) ? tb1[col + 1] : db1[col + 1 - NH];
#pragma unroll
        for (int mt = 0; mt < 4; mt++) {
            const int row = bm + warpM * 64 + mt * 16 + g;
            float2 lo = make_float2(acc[mt][nt][0] + bias0, acc[mt][nt][1] + bias1);
            float2 hi = make_float2(acc[mt][nt][2] + bias0, acc[mt][nt][3] + bias1);
            *reinterpret_cast<float2*>(&g_mid[(size_t)row * MTOT + col]) = lo;
            *reinterpret_cast<float2*>(&g_mid[(size_t)(row + 8) * MTOT + col]) = hi;
        }
    }
}

// ---------------------------------------------------------------------------
// Kernel 2: per-row gating. One warp per batch row.
// ---------------------------------------------------------------------------
__global__ __launch_bounds__(256)
void gating_kernel(const float* __restrict__ tg,
                   const float* __restrict__ tbn,
                   const float* __restrict__ tw2,
                   const float* __restrict__ tb2,
                   const float* __restrict__ lw1,
                   const float* __restrict__ lb1,
                   const float* __restrict__ lw2,
                   const float* __restrict__ lb2,
                   const float* __restrict__ dw2,
                   const float* __restrict__ db2,
                   const float* __restrict__ cw,
                   float* __restrict__ gates_out)  // [BATCH,5]
{
    const int warp = (blockIdx.x * blockDim.x + threadIdx.x) >> 5;
    const int lane = threadIdx.x & 31;
    if (warp >= BATCH) return;

    const float* row = g_mid + (size_t)warp * MTOT;

    // ----- tree nodes: LN + gelu + node logits + softmax(T=0.5) -----
    float pright[NNODES];
#pragma unroll
    for (int n = 0; n < NNODES; n++) {
        float v0 = row[n * 64 + lane];
        float v1 = row[n * 64 + lane + 32];
        float s = v0 + v1;
        float q = v0 * v0 + v1 * v1;
#pragma unroll
        for (int o = 16; o > 0; o >>= 1) {
            s += __shfl_xor_sync(0xffffffffu, s, o);
            q += __shfl_xor_sync(0xffffffffu, q, o);
        }
        float mean = s * (1.0f / 64.0f);
        float var  = q * (1.0f / 64.0f) - mean * mean;
        float rstd = rsqrtf(var + LN_EPS);
        float g0 = gelu_exact((v0 - mean) * rstd * tg[n * 64 + lane] + tbn[n * 64 + lane]);
        float g1 = gelu_exact((v1 - mean) * rstd * tg[n * 64 + lane + 32] + tbn[n * 64 + lane + 32]);
        float z0 = g0 * tw2[n * 128 + lane]      + g1 * tw2[n * 128 + lane + 32];
        float z1 = g0 * tw2[n * 128 + 64 + lane] + g1 * tw2[n * 128 + 64 + lane + 32];
#pragma unroll
        for (int o = 16; o > 0; o >>= 1) {
            z0 += __shfl_xor_sync(0xffffffffu, z0, o);
            z1 += __shfl_xor_sync(0xffffffffu, z1, o);
        }
        z0 += tb2[n * 2 + 0];
        z1 += tb2[n * 2 + 1];
        // softmax([z0,z1]/0.5)[1] = sigmoid(2*(z1-z0))
        pright[n] = 1.0f / (1.0f + expf(-2.0f * (z1 - z0)));
    }

    // ----- leaf probabilities -----
    float leaf[NLEAVES];
#pragma unroll
    for (int l = 0; l < NLEAVES; l++) {
        int b2 = (l >> 2) & 1, b1 = (l >> 1) & 1, b0 = l & 1;
        float p2 = b2 ? pright[0] : (1.0f - pright[0]);
        int n1 = 1 + b2;
        float p1 = b1 ? pright[n1] : (1.0f - pright[n1]);
        int n2 = 3 + b2 * 2 + b1;
        float p0 = b0 ? pright[n2] : (1.0f - pright[n2]);
        leaf[l] = p2 * p1 * p0;
    }

    // ----- tree gate head -----
    float t[2 * NSCALE];
#pragma unroll
    for (int j = 0; j < 2 * NSCALE; j++) {
        float a = lb1[j];
#pragma unroll
        for (int l = 0; l < NLEAVES; l++) a += leaf[l] * lw1[j * NLEAVES + l];
        t[j] = gelu_exact(a);
    }
    float tz[NSCALE];
    float tmax = -1e30f;
#pragma unroll
    for (int sIdx = 0; sIdx < NSCALE; sIdx++) {
        float a = lb2[sIdx];
#pragma unroll
        for (int j = 0; j < 2 * NSCALE; j++) a += t[j] * lw2[sIdx * 2 * NSCALE + j];
        tz[sIdx] = a;
        tmax = fmaxf(tmax, a);
    }
    float tsum = 0.0f;
#pragma unroll
    for (int sIdx = 0; sIdx < NSCALE; sIdx++) { tz[sIdx] = expf(tz[sIdx] - tmax); tsum += tz[sIdx]; }
    float tinv = 1.0f / tsum;
#pragma unroll
    for (int sIdx = 0; sIdx < NSCALE; sIdx++) tz[sIdx] *= tinv;

    // ----- direct gate head -----
    float acc5[NSCALE];
#pragma unroll
    for (int sIdx = 0; sIdx < NSCALE; sIdx++) acc5[sIdx] = 0.0f;
#pragma unroll
    for (int r = 0; r < DH / 32; r++) {
        int idx = r * 32 + lane;
        float dg = gelu_exact(row[NH + idx]);
#pragma unroll
        for (int sIdx = 0; sIdx < NSCALE; sIdx++)
            acc5[sIdx] += dg * dw2[sIdx * DH + idx];
    }
#pragma unroll
    for (int sIdx = 0; sIdx < NSCALE; sIdx++) {
        float a = acc5[sIdx];
#pragma unroll
        for (int o = 16; o > 0; o >>= 1) a += __shfl_xor_sync(0xffffffffu, a, o);
        acc5[sIdx] = a + db2[sIdx];
    }
    float dmax = -1e30f;
#pragma unroll
    for (int sIdx = 0; sIdx < NSCALE; sIdx++) dmax = fmaxf(dmax, acc5[sIdx]);
    float dsum = 0.0f;
#pragma unroll
    for (int sIdx = 0; sIdx < NSCALE; sIdx++) { acc5[sIdx] = expf(acc5[sIdx] - dmax); dsum += acc5[sIdx]; }
    float dinv = 1.0f / dsum;
#pragma unroll
    for (int sIdx = 0; sIdx < NSCALE; sIdx++) acc5[sIdx] *= dinv;

    // ----- combine + renormalize -----
    float w = 1.0f / (1.0f + expf(-cw[0]));
    float gg[NSCALE];
    float gs = 0.0f;
#pragma unroll
    for (int sIdx = 0; sIdx < NSCALE; sIdx++) {
        gg[sIdx] = w * tz[sIdx] + (1.0f - w) * acc5[sIdx];
        gs += gg[sIdx];
    }
    float ginv = 1.0f / gs;
    if (lane < NSCALE)
        gates_out[(size_t)warp * NSCALE + lane] = gg[lane] * ginv;
}

// ---------------------------------------------------------------------------
// Kernel 3: combined[b,d] = sum_s gates[b,s] * logits[s,b,d]
// Streaming loads/stores: one-pass 805 MB, keep it out of L2's way.
// ---------------------------------------------------------------------------
__device__ __forceinline__ float4 ldcs4(const float* p) {
    float4 v;
    asm volatile("ld.global.cs.v4.f32 {%0,%1,%2,%3}, [%4];"
                 : "=f"(v.x), "=f"(v.y), "=f"(v.z), "=f"(v.w) : "l"(p));
    return v;
}
__device__ __forceinline__ void stcs4(float* p, float4 v) {
    asm volatile("st.global.cs.v4.f32 [%0], {%1,%2,%3,%4};"
                 :: "l"(p), "f"(v.x), "f"(v.y), "f"(v.z), "f"(v.w));
}

__global__ __launch_bounds__(256)
void combine_kernel(const float* __restrict__ logits,
                    const float* __restrict__ gates,
                    float* __restrict__ out)
{
    const int b = blockIdx.x;
    const float* gp = gates + (size_t)b * NSCALE;
    float g0 = __ldg(gp + 0), g1 = __ldg(gp + 1), g2 = __ldg(gp + 2),
          g3 = __ldg(gp + 3), g4 = __ldg(gp + 4);

    const size_t rowoff = (size_t)b * DDIM;
    const size_t plane  = (size_t)BATCH * DDIM;

#pragma unroll
    for (int it = 0; it < DDIM / (256 * 4); it++) {
        int col = it * 1024 + threadIdx.x * 4;
        float4 v0 = ldcs4(logits + 0 * plane + rowoff + col);
        float4 v1 = ldcs4(logits + 1 * plane + rowoff + col);
        float4 v2 = ldcs4(logits + 2 * plane + rowoff + col);
        float4 v3 = ldcs4(logits + 3 * plane + rowoff + col);
        float4 v4 = ldcs4(logits + 4 * plane + rowoff + col);
        float4 r;
        r.x = g0 * v0.x + g1 * v1.x + g2 * v2.x + g3 * v3.x + g4 * v4.x;
        r.y = g0 * v0.y + g1 * v1.y + g2 * v2.y + g3 * v3.y + g4 * v4.y;
        r.z = g0 * v0.z + g1 * v1.z + g2 * v2.z + g3 * v3.z + g4 * v4.z;
        r.w = g0 * v0.w + g1 * v1.w + g2 * v2.w + g3 * v3.w + g4 * v4.w;
        stcs4(out + rowoff + col, r);
    }
}

// ---------------------------------------------------------------------------
// Launcher. d_out layout: [combined (8192*4096 f32)] [gates (8192*5 f32)]
// ---------------------------------------------------------------------------
extern "C" void kernel_launch(void* const* d_in, const int* in_sizes, int n_in,
                              void* d_out, int out_size)
{
    const float* features = (const float*)d_in[0];
    const float* logits   = (const float*)d_in[1];
    const float* tw1      = (const float*)d_in[2];
    const float* tb1      = (const float*)d_in[3];
    const float* tg       = (const float*)d_in[4];
    const float* tbn      = (const float*)d_in[5];
    const float* tw2      = (const float*)d_in[6];
    const float* tb2      = (const float*)d_in[7];
    const float* lw1      = (const float*)d_in[8];
    const float* lb1      = (const float*)d_in[9];
    const float* lw2      = (const float*)d_in[10];
    const float* lb2      = (const float*)d_in[11];
    const float* dw1      = (const float*)d_in[12];
    const float* db1      = (const float*)d_in[13];
    const float* dw2      = (const float*)d_in[14];
    const float* db2      = (const float*)d_in[15];
    const float* cw       = (const float*)d_in[16];

    float* out = (float*)d_out;
    float* gates_out = out + (size_t)BATCH * DDIM;

    dim3 gemm_grid(MTOT / BN, BATCH / BM);  // (11, 32)
    gemm_tc_kernel<<<gemm_grid, 256>>>(features, tw1, dw1, tb1, db1);

    gating_kernel<<<BATCH / 8, 256>>>(tg, tbn, tw2, tb2, lw1, lb1, lw2, lb2,
                                      dw2, db2, cw, gates_out);

    combine_kernel<<<BATCH, 256>>>(logits, gates_out, out);
}